// round 6
// baseline (speedup 1.0000x reference)
#include <cuda_runtime.h>
#include <cstdint>

#define D_MODEL 512
#define KEY_DIM 128
#define BS_N 16
#define CTX_PER 1024
#define ARGS_PER 32
#define N_ARGS (BS_N * ARGS_PER)      /* 512  */
#define N_CTX  (BS_N * CTX_PER)       /* 16384 */
#define P_TOT  (N_ARGS * CTX_PER)     /* 524288 */

// Scratch (allocation-free rule: device globals). Accessed ONLY from device
// code -- host-side references give the host shadow symbol (R3 bug).
__device__ float g_Qp[N_ARGS * D_MODEL];   // Qp[r,d] = sum_k arg[r,k] * W[d,k]
__device__ float g_qb[N_ARGS];             // qb[r]   = arg[r,:] . b

// ---------------------------------------------------------------------------
__device__ __forceinline__ uint32_t f2tf32(float f) {
    uint32_t r;
    asm("cvt.rna.tf32.f32 %0, %1;" : "=r"(r) : "f"(f));
    return r;
}

// D(16x8) += A(16x8,row) * B(8x8,col)   tf32 inputs, fp32 accum
__device__ __forceinline__ void mma_tf32(float (&d)[4], const uint32_t (&a)[4],
                                         uint32_t b0, uint32_t b1) {
    asm volatile(
        "mma.sync.aligned.m16n8k8.row.col.f32.tf32.tf32.f32 "
        "{%0,%1,%2,%3}, {%4,%5,%6,%7}, {%8,%9}, {%0,%1,%2,%3};"
        : "+f"(d[0]), "+f"(d[1]), "+f"(d[2]), "+f"(d[3])
        : "r"(a[0]), "r"(a[1]), "r"(a[2]), "r"(a[3]), "r"(b0), "r"(b1));
}

// ---------------------------------------------------------------------------
// Tensor-core GEMM: D[32 x 64] tile of Qrows[32,KD] @ Crows[64,KD]^T
//   256 threads = 8 warps; warp w owns one n8 tile (cols [8w, 8w+8)), both
//   m16 tiles. K chunked by 32, double-buffered smem, tf32 pre-converted.
//   Stride-36 rows -> conflict-free frag loads. 27KB smem -> 2 CTAs/SM.
// LOGITS: Q = g_Qp, adds g_qb, writes logits + rows planes (stride 1024).
// !LOGITS (qp): Q = arg_values, C = W, writes g_Qp (stride 512);
//               blockIdx.x==0 also computes g_qb (quad-shuffle reduction).
// ---------------------------------------------------------------------------
template<int KD, bool LOGITS>
__global__ __launch_bounds__(256, 2) void gemm_tc(const float* __restrict__ Qm,
                                                  const float* __restrict__ Cm,
                                                  const float* __restrict__ bv,
                                                  float* __restrict__ out,
                                                  float* __restrict__ rows_out) {
    constexpr int NCH  = KD / 32;                   // K chunks
    constexpr int OSTR = LOGITS ? CTX_PER : D_MODEL;
    constexpr int TILE_N = 64;

    __shared__ uint32_t Qs[2][32][36];
    __shared__ uint32_t Cs[2][TILE_N][36];

    const int tid  = threadIdx.x;
    const int lane = tid & 31;
    const int warp = tid >> 5;
    const int qr   = lane >> 2;      // fragment groupID  (0..7)
    const int qc   = lane & 3;       // fragment threadID (0..3)

    const float* Qbase = LOGITS ? (const float*)g_Qp : Qm;
    const int qrow_base = blockIdx.y * 32;
    const int crow_base = (LOGITS ? blockIdx.y * CTX_PER : 0) + blockIdx.x * TILE_N;
    const int ocol_base = blockIdx.x * TILE_N;

    // loader indices
    const int lq_row = tid >> 3;                 // 0..31
    const int lq_k   = (tid & 7) * 4;            // 0..28
    const float* qsrc = Qbase + (size_t)(qrow_base + lq_row) * KD + lq_k;

    int lc_row[2], lc_k[2];
    const float* csrc[2];
    #pragma unroll
    for (int j = 0; j < 2; j++) {
        int id = tid + j * 256;
        lc_row[j] = id >> 3;                     // 0..63
        lc_k[j]   = (id & 7) * 4;
        csrc[j] = Cm + (size_t)(crow_base + lc_row[j]) * KD + lc_k[j];
    }

    float acc[2][4] = {};                        // [m-tile][frag]

    // ---- prologue: chunk 0 -> buffer 0
    {
        float4 q = *(const float4*)qsrc;
        *(uint4*)&Qs[0][lq_row][lq_k] =
            make_uint4(f2tf32(q.x), f2tf32(q.y), f2tf32(q.z), f2tf32(q.w));
        #pragma unroll
        for (int j = 0; j < 2; j++) {
            float4 c = *(const float4*)csrc[j];
            *(uint4*)&Cs[0][lc_row[j]][lc_k[j]] =
                make_uint4(f2tf32(c.x), f2tf32(c.y), f2tf32(c.z), f2tf32(c.w));
        }
    }
    __syncthreads();

    const int nbase = warp * 8;                  // warp's n8 tile

    #pragma unroll 1
    for (int it = 0; it < NCH; it++) {
        const int buf = it & 1;

        // prefetch next chunk to registers
        float4 qn;
        float4 cn[2];
        if (it + 1 < NCH) {
            qn = *(const float4*)(qsrc + (it + 1) * 32);
            #pragma unroll
            for (int j = 0; j < 2; j++)
                cn[j] = *(const float4*)(csrc[j] + (it + 1) * 32);
        }

        // compute current chunk: 4 k8 steps
        #pragma unroll
        for (int k8 = 0; k8 < 4; k8++) {
            const int kb = k8 * 8;
            uint32_t b0 = Cs[buf][nbase + qr][kb + qc];
            uint32_t b1 = Cs[buf][nbase + qr][kb + qc + 4];
            #pragma unroll
            for (int mt = 0; mt < 2; mt++) {
                uint32_t a[4];
                a[0] = Qs[buf][mt * 16 + qr    ][kb + qc];
                a[1] = Qs[buf][mt * 16 + qr + 8][kb + qc];
                a[2] = Qs[buf][mt * 16 + qr    ][kb + qc + 4];
                a[3] = Qs[buf][mt * 16 + qr + 8][kb + qc + 4];
                mma_tf32(acc[mt], a, b0, b1);
            }
        }

        // store next chunk into other buffer
        if (it + 1 < NCH) {
            const int nb = buf ^ 1;
            *(uint4*)&Qs[nb][lq_row][lq_k] =
                make_uint4(f2tf32(qn.x), f2tf32(qn.y), f2tf32(qn.z), f2tf32(qn.w));
            #pragma unroll
            for (int j = 0; j < 2; j++) {
                *(uint4*)&Cs[nb][lc_row[j]][lc_k[j]] =
                    make_uint4(f2tf32(cn[j].x), f2tf32(cn[j].y),
                               f2tf32(cn[j].z), f2tf32(cn[j].w));
            }
            __syncthreads();
        }
    }

    // ---- epilogue
    #pragma unroll
    for (int mt = 0; mt < 2; mt++) {
        #pragma unroll
        for (int half = 0; half < 2; half++) {
            const int rg = qrow_base + mt * 16 + qr + half * 8;   // global Q row
            const float qb = LOGITS ? g_qb[rg] : 0.0f;
            const int col = ocol_base + nbase + qc * 2;
            const size_t off = (size_t)rg * OSTR + col;
            float v0 = acc[mt][half * 2 + 0] + qb;
            float v1 = acc[mt][half * 2 + 1] + qb;
            if (LOGITS) {
                *(float2*)(out + off) = make_float2(v0, v1);
                if (rows_out) {
                    float fr = (float)rg;
                    *(float2*)(rows_out + off) = make_float2(fr, fr);
                }
            } else {
                *(float2*)(g_Qp + off) = make_float2(v0, v1);
            }
        }
    }

    // ---- fused qb (qp kernel only, one column of blocks)
    if (!LOGITS && blockIdx.x == 0 && tid < 128) {
        const int row = qrow_base + (tid >> 2);
        const int seg = tid & 3;
        const float* ap = Qm + (size_t)row * KEY_DIM + seg * 32;
        const float* bp = bv + seg * 32;
        float s = 0.f;
        #pragma unroll
        for (int k = 0; k < 8; k++) {
            float4 a  = *(const float4*)(ap + 4 * k);
            float4 bb = *(const float4*)(bp + 4 * k);
            s = fmaf(a.x, bb.x, s); s = fmaf(a.y, bb.y, s);
            s = fmaf(a.z, bb.z, s); s = fmaf(a.w, bb.w, s);
        }
        s += __shfl_xor_sync(0xffffffffu, s, 1);
        s += __shfl_xor_sync(0xffffffffu, s, 2);
        if (seg == 0) g_qb[row] = s;
    }
}

// ---------------------------------------------------------------------------
extern "C" void kernel_launch(void* const* d_in, const int* in_sizes, int n_in,
                              void* d_out, int out_size) {
    // Identify inputs by element count (arg_values and W share 65536 ->
    // disambiguated by order: arg_values precedes W in the input dict).
    const float* argv = nullptr;
    const float* ctxv = nullptr;
    const float* Wm   = nullptr;
    const float* bv   = nullptr;
    int seen_65536 = 0;
    for (int i = 0; i < n_in; i++) {
        long sz = in_sizes[i];
        if (sz == (long)N_CTX * D_MODEL) {
            ctxv = (const float*)d_in[i];
        } else if (sz == (long)N_ARGS * KEY_DIM) {   // == D_MODEL*KEY_DIM too
            if (seen_65536++ == 0) argv = (const float*)d_in[i];
            else                   Wm   = (const float*)d_in[i];
        } else if (sz == KEY_DIM) {
            bv = (const float*)d_in[i];
        }
    }

    float* out        = (float*)d_out;
    float* rows_out   = nullptr;
    float* logits_out = out;
    if (out_size >= 2 * P_TOT) {        // (rows, logits) concatenated
        rows_out   = out;
        logits_out = out + P_TOT;
    }

    // Qp = arg @ W^T (+ fused qb): M=512 rows (16 y-tiles of 32),
    // N=512 dims (8 x-tiles of 64), K=128
    gemm_tc<KEY_DIM, false><<<dim3(8, 16), 256>>>(argv, Wm, bv, nullptr, nullptr);

    // logits: per state (blockIdx.y): [32,1024] = Qp_s @ C_s^T + qb,
    // 16 x-tiles of 64 cols, K=512 -> 256 CTAs, 2 CTAs/SM
    gemm_tc<D_MODEL, true><<<dim3(16, 16), 256>>>(nullptr, ctxv, nullptr,
                                                  logits_out, rows_out);
}